// round 12
// baseline (speedup 1.0000x reference)
#include <cuda_runtime.h>
#include <math.h>

#define Bz 64
#define Tz 512
#define Hz 1024
#define H2z 2048
#define NCTA 128
#define CSZ 2

// Scratch (__device__ globals; no allocation allowed)
__device__ float g_xw[(size_t)32768 * 1024];   // [B*T, H]
__device__ float g_h[Bz * Hz];
__device__ float g_hrnn[Bz * Hz];
__device__ float g_lpp[Bz][128];
__device__ unsigned g_count, g_gen;

typedef unsigned long long ull;
__device__ __forceinline__ ull dup2(float a) {
    ull r; asm("mov.b64 %0,{%1,%1};" : "=l"(r) : "f"(a)); return r;
}
__device__ __forceinline__ void fma2(ull& acc, ull a, ull w) {
    asm("fma.rn.f32x2 %0,%1,%2,%0;" : "+l"(acc) : "l"(a), "l"(w));
}
__device__ __forceinline__ unsigned smem_u32(const void* p) {
    unsigned a;
    asm("{ .reg .u64 t; cvta.to.shared.u64 t, %1; cvt.u32.u64 %0, t; }"
        : "=r"(a) : "l"(p));
    return a;
}

#define CLUSTER_SYNC() do { \
    asm volatile("barrier.cluster.arrive.aligned;" ::: "memory"); \
    asm volatile("barrier.cluster.wait.aligned;"   ::: "memory"); \
} while (0)

// Atomic-counter grid barrier (proven R3/R7/R8).
__device__ __forceinline__ void grid_sync() {
    __syncthreads();
    if (threadIdx.x == 0) {
        unsigned g = *(volatile unsigned*)&g_gen;
        __threadfence();
        unsigned old = atomicAdd(&g_count, 1u);
        if (old == NCTA - 1) {
            g_count = 0u;
            __threadfence();
            atomicAdd(&g_gen, 1u);
        } else {
            while (*(volatile unsigned*)&g_gen == g) { }
        }
        __threadfence();
    }
    __syncthreads();
}

// Persistent-kernel SMEM (~186 KB, 1 CTA/SM)
struct SmemP {
    ull   As2[128][66];      // staged A (f32x2-duplicated), [k_round][row]
    float W1s[512][18];      // w_hh slice: 16 cols x 512 k
    float W2s[512][34];      // w_g slice: 16 std + 16 mu cols x 512 k
    float recv[4 * 64 * 16]; // push buffer: [src 4][row 64][slot 16]
    float red[16];
};

struct SmemX {
    float As[32][66];
    float Ws[32][130];
};

// ---------------------------------------------------------------------------
// Precompute: g_xw = x @ w_ih^T + b_ih + b_hh (R10 verbatim, 2 CTAs/SM)
// ---------------------------------------------------------------------------
__global__ __launch_bounds__(256, 2) void xw_kernel(
    const float* __restrict__ x, const float* __restrict__ w_ih,
    const float* __restrict__ b_ih, const float* __restrict__ b_hh)
{
    __shared__ SmemX s;
    const int n0 = blockIdx.x * 128;
    const int m0 = blockIdx.y * 64;
    const int tid = threadIdx.x;
    const int tx = tid & 15;
    const int ty4 = (tid >> 4) << 2;
    ull acc[4][4] = {};

    const float* A = x + (size_t)m0 * 1024;
    const float* W = w_ih + (size_t)n0 * 1024;
    for (int k0 = 0; k0 < 1024; k0 += 32) {
        #pragma unroll
        for (int i = 0; i < 8; i++) {
            int e = tid + i * 256;
            int row = e >> 5, kk = e & 31;
            s.As[kk][row] = __ldg(&A[row * 1024 + k0 + kk]);
        }
        #pragma unroll
        for (int i = 0; i < 16; i++) {
            int e = tid + i * 256;
            int n = e >> 5, kk = e & 31;
            s.Ws[kk][n] = __ldg(&W[n * 1024 + k0 + kk]);
        }
        __syncthreads();
        #pragma unroll 8
        for (int k = 0; k < 32; k++) {
            float2 a01 = *(const float2*)&s.As[k][ty4];
            float2 a23 = *(const float2*)&s.As[k][ty4 + 2];
            ull ad0 = dup2(a01.x), ad1 = dup2(a01.y);
            ull ad2 = dup2(a23.x), ad3 = dup2(a23.y);
            ull w_[4];
            #pragma unroll
            for (int m = 0; m < 4; m++)
                w_[m] = *(const ull*)&s.Ws[k][m * 32 + tx * 2];
            #pragma unroll
            for (int m = 0; m < 4; m++) {
                fma2(acc[0][m], ad0, w_[m]);
                fma2(acc[1][m], ad1, w_[m]);
                fma2(acc[2][m], ad2, w_[m]);
                fma2(acc[3][m], ad3, w_[m]);
            }
        }
        __syncthreads();
    }
    #pragma unroll
    for (int i = 0; i < 4; i++) {
        size_t m = m0 + ty4 + i;
        #pragma unroll
        for (int m4 = 0; m4 < 4; m4++) {
            int n = n0 + m4 * 32 + tx * 2;
            float2 v = *(float2*)&acc[i][m4];
            v.x += __ldg(&b_ih[n])     + __ldg(&b_hh[n]);
            v.y += __ldg(&b_ih[n + 1]) + __ldg(&b_hh[n + 1]);
            *(float2*)&g_xw[m * Hz + n] = v;
        }
    }
}

// ---------------------------------------------------------------------------
// Persistent recurrent kernel: 128 CTAs x 512 thr, clusters of 2 (capacity 148).
// Cluster c: n-window [16c,16c+16) (G2 also mu 1024+same). CTA r: k [512r,+512).
// ---------------------------------------------------------------------------
__global__ __launch_bounds__(512, 1) __cluster_dims__(CSZ, 1, 1)
void rnn_persistent(
    const float* __restrict__ eps, const float* __restrict__ w_hh,
    const float* __restrict__ w_g, const float* __restrict__ b_g,
    float* __restrict__ o_seq, float* __restrict__ o_prob,
    float* __restrict__ o_mu, float* __restrict__ o_std)
{
    extern __shared__ unsigned char smraw[];
    SmemP& sm = *(SmemP*)smraw;
    const int cta = blockIdx.x;
    const int tid = threadIdx.x;
    const int c = cta >> 1;
    const int r = cta & 1;
    const int n0 = c * 16;
    const int kb = r * 512;
    const float LPC = -0.5f * 1.8378770664093453f * (float)Hz;

    unsigned recv_local = smem_u32(sm.recv);
    unsigned recv_rank[CSZ];
    #pragma unroll
    for (int q = 0; q < CSZ; q++)
        asm("mapa.shared::cluster.u32 %0, %1, %2;"
            : "=r"(recv_rank[q]) : "r"(recv_local), "r"(q));

    g_h[cta * 512 + tid] = 0.0f;

    for (int e = tid; e < 16 * 512; e += 512) {
        int k = e & 511, col = e >> 9;
        sm.W1s[k][col] = __ldg(&w_hh[(size_t)(n0 + col) * 1024 + kb + k]);
    }
    for (int e = tid; e < 32 * 512; e += 512) {
        int k = e & 511, col = e >> 9;
        int row = (col < 16) ? (n0 + col) : (1024 + n0 + (col - 16));
        sm.W2s[k][col] = __ldg(&w_g[(size_t)row * 1024 + kb + k]);
    }
    grid_sync();

    const int hg  = tid >> 8;
    const int wt  = tid & 255;
    const int src = r * 2 + hg;        // 0..3
    const int tx1 = wt & 7,  ty1 = wt >> 3;   // G1: cols 2*tx1, rows 2*ty1+{0,1}
    const int tx2 = wt & 15, ty2 = wt >> 4;   // G2: cols 2*tx2, rows 4*ty2+{0..3}
    const int srow = tid >> 3, si = tid & 7;  // staging

    for (int t = 0; t < Tz; t++) {
        // ---- finalize o_prob(t-1) ---------------------------------------
        if (t > 0 && cta < Bz) {
            float v = (tid < 128) ? __ldcg(&g_lpp[cta][tid]) : 0.f;
            #pragma unroll
            for (int off = 16; off > 0; off >>= 1)
                v += __shfl_xor_sync(0xffffffffu, v, off);
            if ((tid & 31) == 0) sm.red[tid >> 5] = v;
            __syncthreads();
            if (tid == 0) {
                float s = 0.f;
                #pragma unroll
                for (int w = 0; w < 16; w++) s += sm.red[w];
                o_prob[cta * Tz + (t - 1)] = s + LPC;
            }
        }

        // ================= GEMM1: h @ w_hh^T ==============================
        {
            ull acc0 = 0, acc1 = 0;
            for (int p = 0; p < 4; p++) {
                __syncthreads();
                #pragma unroll
                for (int cc = 0; cc < 16; cc++) {
                    int kk = si + cc * 8;
                    float v = __ldcg(&g_h[srow * 1024 + kb + p * 128 + kk]);
                    sm.As2[kk][srow] = dup2(v);
                }
                __syncthreads();
                const int kg = p * 128;
                #pragma unroll 16
                for (int k = hg * 64; k < hg * 64 + 64; k++) {
                    ulonglong2 a = *(const ulonglong2*)&sm.As2[k][ty1 * 2];
                    ull w = *(const ull*)&sm.W1s[kg + k][tx1 * 2];
                    fma2(acc0, a.x, w);
                    fma2(acc1, a.y, w);
                }
            }
            // push to stripe owner: col = 2*tx1; owner = tx1>>2; slot = (tx1&3)*2
            int owner = tx1 >> 2;
            int slot = (tx1 & 3) * 2;
            unsigned base = recv_rank[owner];
            unsigned a0 = base + (unsigned)(((src * 64 + ty1 * 2) * 8 + slot) * 4);
            unsigned a1 = base + (unsigned)(((src * 64 + ty1 * 2 + 1) * 8 + slot) * 4);
            asm volatile("st.shared::cluster.b64 [%0], %1;" :: "r"(a0), "l"(acc0) : "memory");
            asm volatile("st.shared::cluster.b64 [%0], %1;" :: "r"(a1), "l"(acc1) : "memory");
        }
        CLUSTER_SYNC();

        // ---- combine1: 4 srcs + xw + tanh -> g_hrnn (stripe 8 cols) ------
        {
            int b = tid >> 3, sl = tid & 7;      // recv G1 view [4][64][8]
            float s0 = sm.recv[(0 * 64 + b) * 8 + sl] + sm.recv[(1 * 64 + b) * 8 + sl];
            float s1 = sm.recv[(2 * 64 + b) * 8 + sl] + sm.recv[(3 * 64 + b) * 8 + sl];
            int j = n0 + r * 8 + sl;
            float v = __ldg(&g_xw[((size_t)b * Tz + t) * Hz + j]) + s0 + s1;
            g_hrnn[b * 1024 + j] = tanhf(v);
        }
        grid_sync();

        // ================= GEMM2: h_rnn @ w_g^T ===========================
        {
            ull acc[4] = {0, 0, 0, 0};
            for (int p = 0; p < 4; p++) {
                __syncthreads();
                #pragma unroll
                for (int cc = 0; cc < 16; cc++) {
                    int kk = si + cc * 8;
                    float v = __ldcg(&g_hrnn[srow * 1024 + kb + p * 128 + kk]);
                    sm.As2[kk][srow] = dup2(v);
                }
                __syncthreads();
                const int kg = p * 128;
                #pragma unroll 16
                for (int k = hg * 64; k < hg * 64 + 64; k++) {
                    ulonglong2 alo = *(const ulonglong2*)&sm.As2[k][ty2 * 4];
                    ulonglong2 ahi = *(const ulonglong2*)&sm.As2[k][ty2 * 4 + 2];
                    ull w = *(const ull*)&sm.W2s[kg + k][tx2 * 2];
                    fma2(acc[0], alo.x, w);
                    fma2(acc[1], alo.y, w);
                    fma2(acc[2], ahi.x, w);
                    fma2(acc[3], ahi.y, w);
                }
            }
            // push: col = 2*tx2 (0..15 std, 16..31 mu)
            int is_mu = tx2 >> 3;
            int owner = (tx2 >> 2) & 1;
            int slot = is_mu * 8 + (tx2 & 3) * 2;
            unsigned base = recv_rank[owner];
            #pragma unroll
            for (int i = 0; i < 4; i++) {
                unsigned a = base + (unsigned)(((src * 64 + ty2 * 4 + i) * 16 + slot) * 4);
                asm volatile("st.shared::cluster.b64 [%0], %1;"
                             :: "r"(a), "l"(acc[i]) : "memory");
            }
        }
        CLUSTER_SYNC();

        // ---- combine2 + epilogue (stripe: 8 std + 8 mu cols) -------------
        {
            int b = tid >> 3, jl = tid & 7;      // recv G2 view [4][64][16]
            float ss = 0.f, mm = 0.f;
            #pragma unroll
            for (int q = 0; q < 4; q++) {
                ss += sm.recv[(q * 64 + b) * 16 + jl];
                mm += sm.recv[(q * 64 + b) * 16 + 8 + jl];
            }
            int j = n0 + r * 8 + jl;
            ss += __ldg(&b_g[j]);
            mm += __ldg(&b_g[Hz + j]);
            float sd = (ss > 20.f) ? ss : log1pf(__expf(ss));
            float e = __ldg(&eps[((size_t)b * Tz + t) * Hz + j]);
            float smp = mm + sd * e;
            size_t o = ((size_t)b * Tz + t) * Hz + j;
            o_seq[o] = smp;
            o_mu[o]  = mm;
            o_std[o] = sd;
            g_h[b * 1024 + j] = smp;

            float lp = -0.5f * e * e - __logf(sd);
            #pragma unroll
            for (int off = 4; off > 0; off >>= 1)
                lp += __shfl_xor_sync(0xffffffffu, lp, off, 8);
            if (jl == 0) g_lpp[b][c * 2 + r] = lp;
        }
        grid_sync();
    }

    // final o_prob (t = 511)
    if (cta < Bz) {
        float v = (tid < 128) ? __ldcg(&g_lpp[cta][tid]) : 0.f;
        #pragma unroll
        for (int off = 16; off > 0; off >>= 1)
            v += __shfl_xor_sync(0xffffffffu, v, off);
        if ((tid & 31) == 0) sm.red[tid >> 5] = v;
        __syncthreads();
        if (tid == 0) {
            float s = 0.f;
            #pragma unroll
            for (int w = 0; w < 16; w++) s += sm.red[w];
            o_prob[cta * Tz + (Tz - 1)] = s + LPC;
        }
    }
}

// ---------------------------------------------------------------------------
extern "C" void kernel_launch(void* const* d_in, const int* in_sizes, int n_in,
                              void* d_out, int out_size)
{
    const float* x    = (const float*)d_in[0];
    const float* eps  = (const float*)d_in[1];
    const float* w_ih = (const float*)d_in[2];
    const float* w_hh = (const float*)d_in[3];
    const float* b_ih = (const float*)d_in[4];
    const float* b_hh = (const float*)d_in[5];
    const float* w_g  = (const float*)d_in[6];
    const float* b_g  = (const float*)d_in[7];

    float* out = (float*)d_out;
    float* o_seq  = out;
    float* o_prob = out + (size_t)Bz * Tz * Hz;
    float* o_mu   = o_prob + (size_t)Bz * Tz;
    float* o_std  = o_mu + (size_t)Bz * Tz * Hz;

    cudaFuncSetAttribute(rnn_persistent,
                         cudaFuncAttributeMaxDynamicSharedMemorySize,
                         (int)sizeof(SmemP));

    xw_kernel<<<dim3(8, 512), 256>>>(x, w_ih, b_ih, b_hh);
    rnn_persistent<<<NCTA, 512, sizeof(SmemP)>>>(eps, w_hh, w_g, b_g,
                                                 o_seq, o_prob, o_mu, o_std);
}

// round 13
// speedup vs baseline: 1.4595x; 1.4595x over previous
#include <cuda_runtime.h>
#include <math.h>

#define Bz 64
#define Tz 512
#define Hz 1024
#define H2z 2048
#define NCTA 128
#define NS1 16             // GEMM1 k-slices (K=64)
#define NS2 8              // GEMM2 k-slices (K=128)

// Scratch (__device__ globals; no allocation allowed)
__device__ float g_xw[(size_t)32768 * 1024];   // [B*T, H]
__device__ float g_h[Bz * Hz];
__device__ float g_hrnn[Bz * Hz];
__device__ float g_p1[NS1 * Bz * Hz];
__device__ float g_p2[NS2 * Bz * H2z];
__device__ float g_lpp[Bz][2];
__device__ unsigned g_count, g_gen;

typedef unsigned long long ull;
__device__ __forceinline__ ull dup2(float a) {
    ull r; asm("mov.b64 %0,{%1,%1};" : "=l"(r) : "f"(a)); return r;
}
__device__ __forceinline__ void fma2(ull& acc, ull a, ull w) {
    asm("fma.rn.f32x2 %0,%1,%2,%0;" : "+l"(acc) : "l"(a), "l"(w));
}

// Atomic-counter grid barrier (proven R3/R7/R8).
__device__ __forceinline__ void grid_sync() {
    __syncthreads();
    if (threadIdx.x == 0) {
        unsigned g = *(volatile unsigned*)&g_gen;
        __threadfence();
        unsigned old = atomicAdd(&g_count, 1u);
        if (old == NCTA - 1) {
            g_count = 0u;
            __threadfence();
            atomicAdd(&g_gen, 1u);
        } else {
            while (*(volatile unsigned*)&g_gen == g) { }
        }
        __threadfence();
    }
    __syncthreads();
}

// Persistent-kernel SMEM (~168 KB, 1 CTA/SM): resident weights + dup'd A staging
struct SmemR {
    ull   As2[128][66];    // staged A, f32x2-duplicated, [k][row]
    float Ws1[64][130];    // w_hh slice, [k][n]
    float Ws2[128][130];   // w_g  slice, [k][n]
    float red[8];
};

struct SmemX {             // xw kernel staging (proven verbatim)
    float As[32][66];
    float Ws[32][130];
};

// Stage A[64][kcnt] (row-major [64][1024], k-window kb) into As2, duplicated.
__device__ __forceinline__ void stage_A_dup(ull (*As2)[66],
    const float* __restrict__ A, int kb, int kcnt)
{
    const int tid = threadIdx.x;
    const int row = tid >> 2;
    const int cb = (tid & 3) * (kcnt >> 2);
    for (int c = 0; c < (kcnt >> 2); c += 4) {
        float4 v = __ldcg((const float4*)&A[row * 1024 + kb + cb + c]);
        As2[cb + c + 0][row] = dup2(v.x);
        As2[cb + c + 1][row] = dup2(v.y);
        As2[cb + c + 2][row] = dup2(v.z);
        As2[cb + c + 3][row] = dup2(v.w);
    }
}

// Inner GEMM: A pre-duplicated in SMEM, W resident. 22 inst/k, 16 FFMA2/k.
__device__ __forceinline__ void gemm_resident(
    const ull (*As2)[66], const float (*Ws)[130], int kcnt, ull acc[4][4])
{
    const int tid = threadIdx.x;
    const int tx = tid & 15;
    const int ty4 = (tid >> 4) << 2;
    #pragma unroll 8
    for (int k = 0; k < kcnt; k++) {
        ulonglong2 a01 = *(const ulonglong2*)&As2[k][ty4];
        ulonglong2 a23 = *(const ulonglong2*)&As2[k][ty4 + 2];
        ull w_[4];
        #pragma unroll
        for (int m = 0; m < 4; m++)
            w_[m] = *(const ull*)&Ws[k][m * 32 + tx * 2];
        #pragma unroll
        for (int m = 0; m < 4; m++) {
            fma2(acc[0][m], a01.x, w_[m]);
            fma2(acc[1][m], a01.y, w_[m]);
            fma2(acc[2][m], a23.x, w_[m]);
            fma2(acc[3][m], a23.y, w_[m]);
        }
    }
}

__device__ __forceinline__ void store_tile(float* __restrict__ Cp, int ldC,
                                           int n0, ull acc[4][4])
{
    const int tid = threadIdx.x;
    const int tx = tid & 15;
    const int ty4 = (tid >> 4) << 2;
    #pragma unroll
    for (int i = 0; i < 4; i++) {
        int b = ty4 + i;
        #pragma unroll
        for (int m = 0; m < 4; m++)
            *(float2*)&Cp[(size_t)b * ldC + n0 + m * 32 + tx * 2] =
                *(float2*)&acc[i][m];
    }
}

// ---------------------------------------------------------------------------
// Precompute: g_xw = x @ w_ih^T + b_ih + b_hh (proven verbatim, 2 CTAs/SM)
// ---------------------------------------------------------------------------
__global__ __launch_bounds__(256, 2) void xw_kernel(
    const float* __restrict__ x, const float* __restrict__ w_ih,
    const float* __restrict__ b_ih, const float* __restrict__ b_hh)
{
    __shared__ SmemX s;
    const int n0 = blockIdx.x * 128;
    const int m0 = blockIdx.y * 64;
    const int tid = threadIdx.x;
    const int tx = tid & 15;
    const int ty4 = (tid >> 4) << 2;
    ull acc[4][4] = {};

    const float* A = x + (size_t)m0 * 1024;
    const float* W = w_ih + (size_t)n0 * 1024;
    for (int k0 = 0; k0 < 1024; k0 += 32) {
        #pragma unroll
        for (int i = 0; i < 8; i++) {
            int e = tid + i * 256;
            int row = e >> 5, kk = e & 31;
            s.As[kk][row] = __ldg(&A[row * 1024 + k0 + kk]);
        }
        #pragma unroll
        for (int i = 0; i < 16; i++) {
            int e = tid + i * 256;
            int n = e >> 5, kk = e & 31;
            s.Ws[kk][n] = __ldg(&W[n * 1024 + k0 + kk]);
        }
        __syncthreads();
        #pragma unroll 8
        for (int k = 0; k < 32; k++) {
            float2 a01 = *(const float2*)&s.As[k][ty4];
            float2 a23 = *(const float2*)&s.As[k][ty4 + 2];
            ull ad0 = dup2(a01.x), ad1 = dup2(a01.y);
            ull ad2 = dup2(a23.x), ad3 = dup2(a23.y);
            ull w_[4];
            #pragma unroll
            for (int m = 0; m < 4; m++)
                w_[m] = *(const ull*)&s.Ws[k][m * 32 + tx * 2];
            #pragma unroll
            for (int m = 0; m < 4; m++) {
                fma2(acc[0][m], ad0, w_[m]);
                fma2(acc[1][m], ad1, w_[m]);
                fma2(acc[2][m], ad2, w_[m]);
                fma2(acc[3][m], ad3, w_[m]);
            }
        }
        __syncthreads();
    }
    #pragma unroll
    for (int i = 0; i < 4; i++) {
        size_t m = m0 + ty4 + i;
        #pragma unroll
        for (int m4 = 0; m4 < 4; m4++) {
            int n = n0 + m4 * 32 + tx * 2;
            float2 v = *(float2*)&acc[i][m4];
            v.x += __ldg(&b_ih[n])     + __ldg(&b_hh[n]);
            v.y += __ldg(&b_ih[n + 1]) + __ldg(&b_hh[n + 1]);
            *(float2*)&g_xw[m * Hz + n] = v;
        }
    }
}

// ---------------------------------------------------------------------------
// Persistent recurrent kernel: 512 steps, 128 CTAs x 256 threads, 1 CTA/SM.
// GEMM1: 8 n-tiles(128) x 16 sl(K=64). GEMM2: 16 n-tiles(128) x 8 sl(K=128).
// ---------------------------------------------------------------------------
__global__ __launch_bounds__(256, 1) void rnn_persistent(
    const float* __restrict__ eps, const float* __restrict__ w_hh,
    const float* __restrict__ w_g, const float* __restrict__ b_g,
    float* __restrict__ o_seq, float* __restrict__ o_prob,
    float* __restrict__ o_mu, float* __restrict__ o_std)
{
    extern __shared__ unsigned char smraw[];
    SmemR& sm = *(SmemR*)smraw;
    const int cta = blockIdx.x;
    const int tid = threadIdx.x;
    const float LPC = -0.5f * 1.8378770664093453f * (float)Hz;

    const int n01 = (cta & 7)  * 128, kb1 = (cta >> 3) * 64;   // GEMM1 tile
    const int n02 = (cta & 15) * 128, kb2 = (cta >> 4) * 128;  // GEMM2 tile
    const size_t p1off = (size_t)(cta >> 3) * (Bz * Hz);
    const size_t p2off = (size_t)(cta >> 4) * (Bz * H2z);

    // fixed combine coordinates (P1): element pair base
    const int cbase = cta * 512 + tid * 2;
    const int cb_b = cbase >> 10, cb_j = cbase & 1023;
    // fixed epilogue coordinates (P3)
    const int e_b = cta >> 1;
    const int e_j = (cta & 1) * 512 + tid * 2;

    // hoist b_g (constant per thread across all t)
    const float2 bg_s = __ldg((const float2*)&b_g[e_j]);
    const float2 bg_m = __ldg((const float2*)&b_g[Hz + e_j]);

    // zero recurrent state
    g_h[cta * 512 + tid]       = 0.0f;
    g_h[cta * 512 + tid + 256] = 0.0f;

    // preload resident weight slices (once)
    for (int e = tid; e < 128 * 64; e += 256) {
        int k = e & 63, n = e >> 6;
        sm.Ws1[k][n] = __ldg(&w_hh[(size_t)(n01 + n) * 1024 + kb1 + k]);
    }
    for (int e = tid; e < 128 * 128; e += 256) {
        int k = e & 127, n = e >> 7;
        sm.Ws2[k][n] = __ldg(&w_g[(size_t)(n02 + n) * 1024 + kb2 + k]);
    }
    grid_sync();

    for (int t = 0; t < Tz; t++) {
        // ---- P0: GEMM1 partial: g_p1 = h @ w_hh^T + prefetches ------------
        stage_A_dup(sm.As2, g_h, kb1, 64);
        // prefetch static inputs for P1/P3 (overlaps GEMM1 math)
        float2 xw_pf = __ldg((const float2*)
                             &g_xw[((size_t)cb_b * Tz + t) * Hz + cb_j]);
        float2 eps_pf = __ldg((const float2*)
                              &eps[((size_t)e_b * Tz + t) * Hz + e_j]);
        __syncthreads();
        {
            ull acc[4][4] = {};
            gemm_resident(sm.As2, sm.Ws1, 64, acc);
            store_tile(g_p1 + p1off, Hz, n01, acc);
        }
        grid_sync();

        // ---- P1: o_prob(t-1) + combine 16 partials + tanh -> g_hrnn -------
        if (t > 0 && cta < Bz && tid == 0)
            o_prob[cta * Tz + (t - 1)] =
                __ldcg(&g_lpp[cta][0]) + __ldcg(&g_lpp[cta][1]) + LPC;
        {
            float2 v = xw_pf;
            float2 acc2 = make_float2(0.f, 0.f);
            #pragma unroll
            for (int sl = 0; sl < NS1; sl += 2) {
                float2 p0 = __ldcg((const float2*)&g_p1[(size_t)sl * (Bz * Hz) + cbase]);
                float2 p1 = __ldcg((const float2*)&g_p1[(size_t)(sl + 1) * (Bz * Hz) + cbase]);
                v.x += p0.x;    v.y += p0.y;
                acc2.x += p1.x; acc2.y += p1.y;
            }
            v.x += acc2.x; v.y += acc2.y;
            *(float2*)&g_hrnn[cbase] = make_float2(tanhf(v.x), tanhf(v.y));
        }
        grid_sync();

        // ---- P2: GEMM2 partial: g_p2 = h_rnn @ w_g^T ----------------------
        stage_A_dup(sm.As2, g_hrnn, kb2, 128);
        __syncthreads();
        {
            ull acc[4][4] = {};
            gemm_resident(sm.As2, sm.Ws2, 128, acc);
            store_tile(g_p2 + p2off, H2z, n02, acc);
        }
        grid_sync();

        // ---- P3: epilogue, half batch-row per CTA (float2) ----------------
        {
            float2 ss = bg_s;
            float2 mu = bg_m;
            #pragma unroll
            for (int sl = 0; sl < NS2; sl++) {
                const float* p = g_p2 + (size_t)sl * (Bz * H2z) + (size_t)e_b * H2z;
                float2 a = __ldcg((const float2*)&p[e_j]);
                float2 c = __ldcg((const float2*)&p[Hz + e_j]);
                ss.x += a.x; ss.y += a.y;
                mu.x += c.x; mu.y += c.y;
            }
            float sdx = (ss.x > 20.f) ? ss.x : log1pf(__expf(ss.x));
            float sdy = (ss.y > 20.f) ? ss.y : log1pf(__expf(ss.y));
            float2 smp = make_float2(mu.x + sdx * eps_pf.x,
                                     mu.y + sdy * eps_pf.y);
            size_t o = ((size_t)e_b * Tz + t) * Hz + e_j;
            *(float2*)&o_seq[o] = smp;
            *(float2*)&o_mu[o]  = mu;
            *(float2*)&o_std[o] = make_float2(sdx, sdy);
            *(float2*)&g_h[e_b * Hz + e_j] = smp;

            float lp = -0.5f * (eps_pf.x * eps_pf.x + eps_pf.y * eps_pf.y)
                     - __logf(sdx) - __logf(sdy);
            #pragma unroll
            for (int off = 16; off > 0; off >>= 1)
                lp += __shfl_xor_sync(0xffffffffu, lp, off);
            if ((tid & 31) == 0) sm.red[tid >> 5] = lp;
            __syncthreads();
            if (tid == 0) {
                float sum = 0.0f;
                #pragma unroll
                for (int w = 0; w < 8; w++) sum += sm.red[w];
                g_lpp[e_b][cta & 1] = sum;
            }
        }
        grid_sync();
    }

    // final o_prob for t = 511
    if (cta < Bz && tid == 0)
        o_prob[cta * Tz + (Tz - 1)] =
            __ldcg(&g_lpp[cta][0]) + __ldcg(&g_lpp[cta][1]) + LPC;
}

// ---------------------------------------------------------------------------
extern "C" void kernel_launch(void* const* d_in, const int* in_sizes, int n_in,
                              void* d_out, int out_size)
{
    const float* x    = (const float*)d_in[0];
    const float* eps  = (const float*)d_in[1];
    const float* w_ih = (const float*)d_in[2];
    const float* w_hh = (const float*)d_in[3];
    const float* b_ih = (const float*)d_in[4];
    const float* b_hh = (const float*)d_in[5];
    const float* w_g  = (const float*)d_in[6];
    const float* b_g  = (const float*)d_in[7];

    float* out = (float*)d_out;
    float* o_seq  = out;
    float* o_prob = out + (size_t)Bz * Tz * Hz;
    float* o_mu   = o_prob + (size_t)Bz * Tz;
    float* o_std  = o_mu + (size_t)Bz * Tz * Hz;

    cudaFuncSetAttribute(rnn_persistent,
                         cudaFuncAttributeMaxDynamicSharedMemorySize,
                         (int)sizeof(SmemR));

    xw_kernel<<<dim3(8, 512), 256>>>(x, w_ih, b_ih, b_hh);
    rnn_persistent<<<NCTA, 256, sizeof(SmemR)>>>(eps, w_hh, w_g, b_g,
                                                 o_seq, o_prob, o_mu, o_std);
}

// round 14
// speedup vs baseline: 1.4752x; 1.0108x over previous
#include <cuda_runtime.h>
#include <math.h>

#define Bz 64
#define Tz 512
#define Hz 1024
#define H2z 2048
#define NCTA 128
#define NS1 16             // GEMM1 k-slices (K=64)
#define NS2 8              // GEMM2 k-slices (K=128)

// Scratch (__device__ globals; no allocation allowed)
__device__ float g_xw[(size_t)32768 * 1024];   // [B*T, H]
__device__ float g_hrnn[Bz * Hz];
__device__ float g_p1[NS1 * Bz * Hz];
__device__ float g_p2[NS2 * Bz * H2z];
__device__ float g_lpp[Bz][16];                // [row][col-window]
__device__ unsigned g_count, g_gen;

typedef unsigned long long ull;
__device__ __forceinline__ ull dup2(float a) {
    ull r; asm("mov.b64 %0,{%1,%1};" : "=l"(r) : "f"(a)); return r;
}
__device__ __forceinline__ void fma2(ull& acc, ull a, ull w) {
    asm("fma.rn.f32x2 %0,%1,%2,%0;" : "+l"(acc) : "l"(a), "l"(w));
}

// Atomic-counter grid barrier (proven R3/R7/R8).
__device__ __forceinline__ void grid_sync() {
    __syncthreads();
    if (threadIdx.x == 0) {
        unsigned g = *(volatile unsigned*)&g_gen;
        __threadfence();
        unsigned old = atomicAdd(&g_count, 1u);
        if (old == NCTA - 1) {
            g_count = 0u;
            __threadfence();
            atomicAdd(&g_gen, 1u);
        } else {
            while (*(volatile unsigned*)&g_gen == g) { }
        }
        __threadfence();
    }
    __syncthreads();
}

// Persistent-kernel SMEM (~131 KB): resident weights + A staging
struct SmemR {
    float As[128][66];     // staged A, [k][row]
    float Ws1[64][130];    // w_hh slice, [k][n]
    float Ws2[128][130];   // w_g  slice, [k][n]
    float red[8];
};

struct SmemX {             // xw kernel staging (proven verbatim)
    float As[32][66];
    float Ws[32][130];
};

// Stage A[64][kcnt] (row-major [64][1024], k-window kb) into As (R8 verbatim).
__device__ __forceinline__ void stage_A(float (*As)[66],
    const float* __restrict__ A, int kb, int kcnt)
{
    const int tid = threadIdx.x;
    const int row = tid >> 2;
    const int cb = (tid & 3) * (kcnt >> 2);
    for (int c = 0; c < (kcnt >> 2); c += 4) {
        float4 v = __ldcg((const float4*)&A[row * 1024 + kb + cb + c]);
        As[cb + c + 0][row] = v.x;
        As[cb + c + 1][row] = v.y;
        As[cb + c + 2][row] = v.z;
        As[cb + c + 3][row] = v.w;
    }
}

// Inner GEMM (R8 verbatim): A float in SMEM (dup2 in loop), W resident.
__device__ __forceinline__ void gemm_resident(
    const float (*As)[66], const float (*Ws)[130], int kcnt, ull acc[4][4])
{
    const int tid = threadIdx.x;
    const int tx = tid & 15;
    const int ty4 = (tid >> 4) << 2;
    #pragma unroll 8
    for (int k = 0; k < kcnt; k++) {
        float2 a01 = *(const float2*)&As[k][ty4];
        float2 a23 = *(const float2*)&As[k][ty4 + 2];
        ull ad0 = dup2(a01.x), ad1 = dup2(a01.y);
        ull ad2 = dup2(a23.x), ad3 = dup2(a23.y);
        ull w_[4];
        #pragma unroll
        for (int m = 0; m < 4; m++)
            w_[m] = *(const ull*)&Ws[k][m * 32 + tx * 2];
        #pragma unroll
        for (int m = 0; m < 4; m++) {
            fma2(acc[0][m], ad0, w_[m]);
            fma2(acc[1][m], ad1, w_[m]);
            fma2(acc[2][m], ad2, w_[m]);
            fma2(acc[3][m], ad3, w_[m]);
        }
    }
}

__device__ __forceinline__ void store_tile(float* __restrict__ Cp, int ldC,
                                           int n0, ull acc[4][4])
{
    const int tid = threadIdx.x;
    const int tx = tid & 15;
    const int ty4 = (tid >> 4) << 2;
    #pragma unroll
    for (int i = 0; i < 4; i++) {
        int b = ty4 + i;
        #pragma unroll
        for (int m = 0; m < 4; m++)
            *(float2*)&Cp[(size_t)b * ldC + n0 + m * 32 + tx * 2] =
                *(float2*)&acc[i][m];
    }
}

// ---------------------------------------------------------------------------
// Precompute: g_xw = x @ w_ih^T + b_ih + b_hh (proven verbatim, 2 CTAs/SM)
// ---------------------------------------------------------------------------
__global__ __launch_bounds__(256, 2) void xw_kernel(
    const float* __restrict__ x, const float* __restrict__ w_ih,
    const float* __restrict__ b_ih, const float* __restrict__ b_hh)
{
    __shared__ SmemX s;
    const int n0 = blockIdx.x * 128;
    const int m0 = blockIdx.y * 64;
    const int tid = threadIdx.x;
    const int tx = tid & 15;
    const int ty4 = (tid >> 4) << 2;
    ull acc[4][4] = {};

    const float* A = x + (size_t)m0 * 1024;
    const float* W = w_ih + (size_t)n0 * 1024;
    for (int k0 = 0; k0 < 1024; k0 += 32) {
        #pragma unroll
        for (int i = 0; i < 8; i++) {
            int e = tid + i * 256;
            int row = e >> 5, kk = e & 31;
            s.As[kk][row] = __ldg(&A[row * 1024 + k0 + kk]);
        }
        #pragma unroll
        for (int i = 0; i < 16; i++) {
            int e = tid + i * 256;
            int n = e >> 5, kk = e & 31;
            s.Ws[kk][n] = __ldg(&W[n * 1024 + k0 + kk]);
        }
        __syncthreads();
        #pragma unroll 8
        for (int k = 0; k < 32; k++) {
            float2 a01 = *(const float2*)&s.As[k][ty4];
            float2 a23 = *(const float2*)&s.As[k][ty4 + 2];
            ull ad0 = dup2(a01.x), ad1 = dup2(a01.y);
            ull ad2 = dup2(a23.x), ad3 = dup2(a23.y);
            ull w_[4];
            #pragma unroll
            for (int m = 0; m < 4; m++)
                w_[m] = *(const ull*)&s.Ws[k][m * 32 + tx * 2];
            #pragma unroll
            for (int m = 0; m < 4; m++) {
                fma2(acc[0][m], ad0, w_[m]);
                fma2(acc[1][m], ad1, w_[m]);
                fma2(acc[2][m], ad2, w_[m]);
                fma2(acc[3][m], ad3, w_[m]);
            }
        }
        __syncthreads();
    }
    #pragma unroll
    for (int i = 0; i < 4; i++) {
        size_t m = m0 + ty4 + i;
        #pragma unroll
        for (int m4 = 0; m4 < 4; m4++) {
            int n = n0 + m4 * 32 + tx * 2;
            float2 v = *(float2*)&acc[i][m4];
            v.x += __ldg(&b_ih[n])     + __ldg(&b_hh[n]);
            v.y += __ldg(&b_ih[n + 1]) + __ldg(&b_hh[n + 1]);
            *(float2*)&g_xw[m * Hz + n] = v;
        }
    }
}

// ---------------------------------------------------------------------------
// Persistent recurrent kernel: 512 steps, 128 CTAs x 256 threads, 1 CTA/SM.
// 3 phases/step:
//   P0: fused epilogue(t-1) -> h staged in SMEM (+owner output writes) + GEMM1
//   P1: o_prob(t-1) + combine partials + tanh -> g_hrnn
//   P2: stage h_rnn + GEMM2 -> g_p2
// ---------------------------------------------------------------------------
__global__ __launch_bounds__(256, 1) void rnn_persistent(
    const float* __restrict__ eps, const float* __restrict__ w_hh,
    const float* __restrict__ w_g, const float* __restrict__ b_g,
    float* __restrict__ o_seq, float* __restrict__ o_prob,
    float* __restrict__ o_mu, float* __restrict__ o_std)
{
    extern __shared__ unsigned char smraw[];
    SmemR& sm = *(SmemR*)smraw;
    const int cta = blockIdx.x;
    const int tid = threadIdx.x;
    const float LPC = -0.5f * 1.8378770664093453f * (float)Hz;

    const int n01 = (cta & 7)  * 128, kb1 = (cta >> 3) * 64;   // GEMM1 tile
    const int n02 = (cta & 15) * 128, kb2 = (cta >> 4) * 128;  // GEMM2 tile
    const size_t p1off = (size_t)(cta >> 3) * (Bz * Hz);
    const size_t p2off = (size_t)(cta >> 4) * (Bz * H2z);

    // fused-epilogue coordinates: warp wrp handles rows 8*wrp..8*wrp+7,
    // lane handles col-pair jp within this CTA's GEMM1 k-window [kb1, kb1+64)
    const int lane = tid & 31;
    const int wrp  = tid >> 5;
    const int jp   = kb1 + 2 * lane;
    const bool owner = (cta & 7) == 0;    // 1 of 8 CTAs per window writes outputs
    const int win = cta >> 3;             // 0..15

    // b_g hoist (fixed jp per thread)
    const float2 bg_s = __ldg((const float2*)&b_g[jp]);
    const float2 bg_m = __ldg((const float2*)&b_g[Hz + jp]);

    // combine coordinates (P1)
    const int cbase = cta * 512 + tid * 2;

    // preload resident weight slices (once)
    for (int e = tid; e < 128 * 64; e += 256) {
        int k = e & 63, n = e >> 6;
        sm.Ws1[k][n] = __ldg(&w_hh[(size_t)(n01 + n) * 1024 + kb1 + k]);
    }
    for (int e = tid; e < 128 * 128; e += 256) {
        int k = e & 127, n = e >> 7;
        sm.Ws2[k][n] = __ldg(&w_g[(size_t)(n02 + n) * 1024 + kb2 + k]);
    }
    grid_sync();

    for (int t = 0; t < Tz; t++) {
        // ---- P0: fused epilogue(t-1) -> SMEM stage; then GEMM1 -------------
        if (t > 0) {
            #pragma unroll 2
            for (int i = 0; i < 8; i++) {
                int b = wrp * 8 + i;
                float2 ss = bg_s, mu = bg_m;
                #pragma unroll
                for (int sl = 0; sl < NS2; sl++) {
                    const float* p = g_p2 + (size_t)sl * (Bz * H2z)
                                   + (size_t)b * H2z;
                    float2 a = __ldcg((const float2*)&p[jp]);
                    float2 c = __ldcg((const float2*)&p[Hz + jp]);
                    ss.x += a.x; ss.y += a.y;
                    mu.x += c.x; mu.y += c.y;
                }
                float sdx = (ss.x > 20.f) ? ss.x : log1pf(__expf(ss.x));
                float sdy = (ss.y > 20.f) ? ss.y : log1pf(__expf(ss.y));
                float2 e = __ldg((const float2*)
                                 &eps[((size_t)b * Tz + (t - 1)) * Hz + jp]);
                float hx = mu.x + sdx * e.x;
                float hy = mu.y + sdy * e.y;
                sm.As[2 * lane][b]     = hx;
                sm.As[2 * lane + 1][b] = hy;
                if (owner) {
                    size_t o = ((size_t)b * Tz + (t - 1)) * Hz + jp;
                    *(float2*)&o_seq[o] = make_float2(hx, hy);
                    *(float2*)&o_mu[o]  = mu;
                    *(float2*)&o_std[o] = make_float2(sdx, sdy);
                    float lp = -0.5f * (e.x * e.x + e.y * e.y)
                             - __logf(sdx) - __logf(sdy);
                    #pragma unroll
                    for (int off = 16; off > 0; off >>= 1)
                        lp += __shfl_xor_sync(0xffffffffu, lp, off);
                    if (lane == 0) g_lpp[b][win] = lp;
                }
            }
        } else {
            #pragma unroll
            for (int i = 0; i < 8; i++) {
                sm.As[2 * lane][wrp * 8 + i]     = 0.0f;
                sm.As[2 * lane + 1][wrp * 8 + i] = 0.0f;
            }
        }
        __syncthreads();
        {
            ull acc[4][4] = {};
            gemm_resident(sm.As, sm.Ws1, 64, acc);
            store_tile(g_p1 + p1off, Hz, n01, acc);
        }
        grid_sync();

        // ---- P1: o_prob(t-1) + combine 16 partials + tanh -> g_hrnn --------
        if (t > 0 && cta < Bz && tid == 0) {
            float s = 0.f;
            #pragma unroll
            for (int w = 0; w < 16; w++) s += __ldcg(&g_lpp[cta][w]);
            o_prob[cta * Tz + (t - 1)] = s + LPC;
        }
        {
            int b = cbase >> 10, j = cbase & 1023;
            float2 v = __ldg((const float2*)&g_xw[((size_t)b * Tz + t) * Hz + j]);
            float2 acc2 = make_float2(0.f, 0.f);
            #pragma unroll
            for (int sl = 0; sl < NS1; sl += 2) {
                float2 p0 = __ldcg((const float2*)&g_p1[(size_t)sl * (Bz * Hz) + cbase]);
                float2 p1 = __ldcg((const float2*)&g_p1[(size_t)(sl + 1) * (Bz * Hz) + cbase]);
                v.x += p0.x;    v.y += p0.y;
                acc2.x += p1.x; acc2.y += p1.y;
            }
            v.x += acc2.x; v.y += acc2.y;
            *(float2*)&g_hrnn[cbase] = make_float2(tanhf(v.x), tanhf(v.y));
        }
        grid_sync();

        // ---- P2: stage h_rnn + GEMM2 -> g_p2 --------------------------------
        stage_A(sm.As, g_hrnn, kb2, 128);
        __syncthreads();
        {
            ull acc[4][4] = {};
            gemm_resident(sm.As, sm.Ws2, 128, acc);
            store_tile(g_p2 + p2off, H2z, n02, acc);
        }
        grid_sync();
    }

    // ---- tail: epilogue for t = 511 (owners only) + o_prob ----------------
    if (owner) {
        #pragma unroll 2
        for (int i = 0; i < 8; i++) {
            int b = wrp * 8 + i;
            float2 ss = bg_s, mu = bg_m;
            #pragma unroll
            for (int sl = 0; sl < NS2; sl++) {
                const float* p = g_p2 + (size_t)sl * (Bz * H2z) + (size_t)b * H2z;
                float2 a = __ldcg((const float2*)&p[jp]);
                float2 c = __ldcg((const float2*)&p[Hz + jp]);
                ss.x += a.x; ss.y += a.y;
                mu.x += c.x; mu.y += c.y;
            }
            float sdx = (ss.x > 20.f) ? ss.x : log1pf(__expf(ss.x));
            float sdy = (ss.y > 20.f) ? ss.y : log1pf(__expf(ss.y));
            float2 e = __ldg((const float2*)
                             &eps[((size_t)b * Tz + (Tz - 1)) * Hz + jp]);
            float hx = mu.x + sdx * e.x;
            float hy = mu.y + sdy * e.y;
            size_t o = ((size_t)b * Tz + (Tz - 1)) * Hz + jp;
            *(float2*)&o_seq[o] = make_float2(hx, hy);
            *(float2*)&o_mu[o]  = mu;
            *(float2*)&o_std[o] = make_float2(sdx, sdy);
            float lp = -0.5f * (e.x * e.x + e.y * e.y)
                     - __logf(sdx) - __logf(sdy);
            #pragma unroll
            for (int off = 16; off > 0; off >>= 1)
                lp += __shfl_xor_sync(0xffffffffu, lp, off);
            if (lane == 0) g_lpp[b][win] = lp;
        }
    }
    grid_sync();
    if (cta < Bz && tid == 0) {
        float s = 0.f;
        #pragma unroll
        for (int w = 0; w < 16; w++) s += __ldcg(&g_lpp[cta][w]);
        o_prob[cta * Tz + (Tz - 1)] = s + LPC;
    }
}

// ---------------------------------------------------------------------------
extern "C" void kernel_launch(void* const* d_in, const int* in_sizes, int n_in,
                              void* d_out, int out_size)
{
    const float* x    = (const float*)d_in[0];
    const float* eps  = (const float*)d_in[1];
    const float* w_ih = (const float*)d_in[2];
    const float* w_hh = (const float*)d_in[3];
    const float* b_ih = (const float*)d_in[4];
    const float* b_hh = (const float*)d_in[5];
    const float* w_g  = (const float*)d_in[6];
    const float* b_g  = (const float*)d_in[7];

    float* out = (float*)d_out;
    float* o_seq  = out;
    float* o_prob = out + (size_t)Bz * Tz * Hz;
    float* o_mu   = o_prob + (size_t)Bz * Tz;
    float* o_std  = o_mu + (size_t)Bz * Tz * Hz;

    cudaFuncSetAttribute(rnn_persistent,
                         cudaFuncAttributeMaxDynamicSharedMemorySize,
                         (int)sizeof(SmemR));

    xw_kernel<<<dim3(8, 512), 256>>>(x, w_ih, b_ih, b_hh);
    rnn_persistent<<<NCTA, 256, sizeof(SmemR)>>>(eps, w_hh, w_g, b_g,
                                                 o_seq, o_prob, o_mu, o_std);
}

// round 16
// speedup vs baseline: 1.6486x; 1.1175x over previous
#include <cuda_runtime.h>
#include <cuda_bf16.h>
#include <math.h>
#include <stdint.h>

#define Bz 64
#define Tz 512
#define Hz 1024
#define H2z 2048
#define NCTA 128
#define NS1 16             // GEMM1 k-slices (K=64)
#define NS2 8              // GEMM2 k-slices (K=128)
#define APAD 72            // bf16 row stride in SMEM (64 + 8 pad)

// Scratch (__device__ globals; no allocation allowed)
__device__ float g_xw[(size_t)32768 * 1024];   // [B*T, H]
__device__ float g_h[Bz * Hz];
__device__ float g_hrnn[Bz * Hz];
__device__ float g_p1[NS1 * Bz * Hz];
__device__ float g_p2[NS2 * Bz * H2z];
__device__ float g_lpp[Bz][2];
__device__ unsigned g_count, g_gen;

typedef unsigned long long ull;
__device__ __forceinline__ ull dup2(float a) {
    ull r; asm("mov.b64 %0,{%1,%1};" : "=l"(r) : "f"(a)); return r;
}
__device__ __forceinline__ void fma2(ull& acc, ull a, ull w) {
    asm("fma.rn.f32x2 %0,%1,%2,%0;" : "+l"(acc) : "l"(a), "l"(w));
}
__device__ __forceinline__ uint32_t smem_u32(const void* p) {
    uint32_t a;
    asm("{ .reg .u64 t; cvta.to.shared.u64 t, %1; cvt.u32.u64 %0, t; }"
        : "=r"(a) : "l"(p));
    return a;
}

// Atomic-counter grid barrier (proven R3/R7/R8).
__device__ __forceinline__ void grid_sync() {
    __syncthreads();
    if (threadIdx.x == 0) {
        unsigned g = *(volatile unsigned*)&g_gen;
        __threadfence();
        unsigned old = atomicAdd(&g_count, 1u);
        if (old == NCTA - 1) {
            g_count = 0u;
            __threadfence();
            atomicAdd(&g_gen, 1u);
        } else {
            while (*(volatile unsigned*)&g_gen == g) { }
        }
        __threadfence();
    }
    __syncthreads();
}

// ===========================================================================
// mma.sync helpers (baseline PTX — no arch-feature suffix required)
// ===========================================================================
__device__ __forceinline__ void ldmA(uint32_t addr, uint32_t r[4]) {
    asm volatile("ldmatrix.sync.aligned.m8n8.x4.shared.b16 {%0,%1,%2,%3}, [%4];"
                 : "=r"(r[0]), "=r"(r[1]), "=r"(r[2]), "=r"(r[3]) : "r"(addr));
}
__device__ __forceinline__ void ldmB(uint32_t addr, uint32_t r[2]) {
    asm volatile("ldmatrix.sync.aligned.m8n8.x2.shared.b16 {%0,%1}, [%2];"
                 : "=r"(r[0]), "=r"(r[1]) : "r"(addr));
}
__device__ __forceinline__ void mma16816(float d[4], const uint32_t a[4],
                                         const uint32_t b[2]) {
    asm volatile(
        "mma.sync.aligned.m16n8k16.row.col.f32.bf16.bf16.f32 "
        "{%0,%1,%2,%3},{%4,%5,%6,%7},{%8,%9},{%0,%1,%2,%3};"
        : "+f"(d[0]), "+f"(d[1]), "+f"(d[2]), "+f"(d[3])
        : "r"(a[0]), "r"(a[1]), "r"(a[2]), "r"(a[3]), "r"(b[0]), "r"(b[1]));
}

// split fp32x4 -> hi/lo bf16x2 pairs
__device__ __forceinline__ void split4(float4 v, uint2& hi, uint2& lo) {
    __nv_bfloat162 h0 = __floats2bfloat162_rn(v.x, v.y);
    __nv_bfloat162 h1 = __floats2bfloat162_rn(v.z, v.w);
    float2 f0 = __bfloat1622float2(h0);
    float2 f1 = __bfloat1622float2(h1);
    __nv_bfloat162 l0 = __floats2bfloat162_rn(v.x - f0.x, v.y - f0.y);
    __nv_bfloat162 l1 = __floats2bfloat162_rn(v.z - f1.x, v.w - f1.y);
    hi = make_uint2(*(uint32_t*)&h0, *(uint32_t*)&h1);
    lo = make_uint2(*(uint32_t*)&l0, *(uint32_t*)&l1);
}

// ===========================================================================
// xw_mma: g_xw = x @ w_ih^T + b_ih + b_hh via mma.sync bf16 2-split.
// CTA tile 128(M) x 64(N), 8 warps (4m x 2n), K chunks of 64.
// ===========================================================================
__global__ __launch_bounds__(256, 2) void xw_mma(
    const float* __restrict__ x, const float* __restrict__ w_ih,
    const float* __restrict__ b_ih, const float* __restrict__ b_hh)
{
    extern __shared__ __nv_bfloat16 sb[];
    // layout: A_hi [128][APAD], A_lo [128][APAD], B_hi [64][APAD], B_lo [64][APAD]
    __nv_bfloat16* Ah = sb;
    __nv_bfloat16* Al = sb + 128 * APAD;
    __nv_bfloat16* Bh = sb + 256 * APAD;
    __nv_bfloat16* Bl = sb + 256 * APAD + 64 * APAD;

    const int tid = threadIdx.x;
    const int lane = tid & 31;
    const int wid = tid >> 5;
    const int m0 = blockIdx.y * 128;
    const int n0 = blockIdx.x * 64;
    const int m_w = (wid >> 1) * 32;
    const int n_w = (wid & 1) * 32;

    const uint32_t aHiB = smem_u32(Ah);
    const uint32_t aLoB = smem_u32(Al);
    const uint32_t bHiB = smem_u32(Bh);
    const uint32_t bLoB = smem_u32(Bl);

    // ldmatrix address offsets (bytes), fixed per thread
    const uint32_t aoff0 = (uint32_t)((m_w + (lane & 15)) * (APAD * 2) + (lane >> 4) * 16);
    const uint32_t aoff1 = aoff0 + 16 * (APAD * 2);
    const uint32_t boffbase = (uint32_t)((n_w + (lane & 7)) * (APAD * 2)
                                         + ((lane >> 3) & 1) * 16);

    float acc[2][4][4] = {};   // [fm][fn][reg]

    for (int c = 0; c < 16; c++) {
        const int k0 = c * 64;
        __syncthreads();
        // ---- stage A chunk: 128 x 64 fp32 -> split bf16 (8 float4/thread)
        #pragma unroll
        for (int i = 0; i < 8; i++) {
            int idx = tid + i * 256;
            int row = idx >> 4, kq = idx & 15;
            float4 v = __ldg((const float4*)&x[(size_t)(m0 + row) * 1024 + k0 + kq * 4]);
            uint2 hi, lo;
            split4(v, hi, lo);
            *(uint2*)&Ah[row * APAD + kq * 4] = hi;
            *(uint2*)&Al[row * APAD + kq * 4] = lo;
        }
        // ---- stage B chunk: 64 x 64 fp32 -> split bf16 (4 float4/thread)
        #pragma unroll
        for (int i = 0; i < 4; i++) {
            int idx = tid + i * 256;
            int row = idx >> 4, kq = idx & 15;
            float4 v = __ldg((const float4*)&w_ih[(size_t)(n0 + row) * 1024 + k0 + kq * 4]);
            uint2 hi, lo;
            split4(v, hi, lo);
            *(uint2*)&Bh[row * APAD + kq * 4] = hi;
            *(uint2*)&Bl[row * APAD + kq * 4] = lo;
        }
        __syncthreads();

        // ---- 4 k16 sub-chunks x (hi.hi + hi.lo + lo.hi) -------------------
        #pragma unroll
        for (int kk = 0; kk < 4; kk++) {
            const uint32_t kb = kk * 32;   // 16 bf16 = 32 bytes
            uint32_t ah0[4], ah1[4], al0[4], al1[4];
            ldmA(aHiB + aoff0 + kb, ah0);
            ldmA(aHiB + aoff1 + kb, ah1);
            ldmA(aLoB + aoff0 + kb, al0);
            ldmA(aLoB + aoff1 + kb, al1);
            uint32_t bh[4][2], bl[4][2];
            #pragma unroll
            for (int fn = 0; fn < 4; fn++) {
                ldmB(bHiB + boffbase + fn * 8 * (APAD * 2) + kb, bh[fn]);
                ldmB(bLoB + boffbase + fn * 8 * (APAD * 2) + kb, bl[fn]);
            }
            #pragma unroll
            for (int fn = 0; fn < 4; fn++) {
                mma16816(acc[0][fn], ah0, bh[fn]);
                mma16816(acc[1][fn], ah1, bh[fn]);
                mma16816(acc[0][fn], ah0, bl[fn]);
                mma16816(acc[1][fn], ah1, bl[fn]);
                mma16816(acc[0][fn], al0, bh[fn]);
                mma16816(acc[1][fn], al1, bh[fn]);
            }
        }
    }

    // ---- write D + biases ---------------------------------------------
    #pragma unroll
    for (int fm = 0; fm < 2; fm++) {
        int mr = m0 + m_w + fm * 16 + (lane >> 2);
        #pragma unroll
        for (int fn = 0; fn < 4; fn++) {
            int nc = n0 + n_w + fn * 8 + 2 * (lane & 3);
            float bx = __ldg(&b_ih[nc])     + __ldg(&b_hh[nc]);
            float by = __ldg(&b_ih[nc + 1]) + __ldg(&b_hh[nc + 1]);
            *(float2*)&g_xw[(size_t)mr * Hz + nc] =
                make_float2(acc[fm][fn][0] + bx, acc[fm][fn][1] + by);
            *(float2*)&g_xw[(size_t)(mr + 8) * Hz + nc] =
                make_float2(acc[fm][fn][2] + bx, acc[fm][fn][3] + by);
        }
    }
}

// ===========================================================================
// Persistent recurrent kernel — EXACT R8 (proven 12.89 ms).
// ===========================================================================
struct SmemR {
    float As[128][66];     // staged A, [k][row]
    float Ws1[64][130];    // w_hh slice, [k][n]
    float Ws2[128][130];   // w_g  slice, [k][n]
    float red[8];
};

__device__ __forceinline__ void stage_A(float (*As)[66],
    const float* __restrict__ A, int kb, int kcnt)
{
    const int tid = threadIdx.x;
    const int row = tid >> 2;
    const int cb = (tid & 3) * (kcnt >> 2);
    for (int c = 0; c < (kcnt >> 2); c += 4) {
        float4 v = __ldcg((const float4*)&A[row * 1024 + kb + cb + c]);
        As[cb + c + 0][row] = v.x;
        As[cb + c + 1][row] = v.y;
        As[cb + c + 2][row] = v.z;
        As[cb + c + 3][row] = v.w;
    }
}

__device__ __forceinline__ void gemm_resident(
    const float (*As)[66], const float (*Ws)[130], int kcnt, ull acc[4][4])
{
    const int tid = threadIdx.x;
    const int tx = tid & 15;
    const int ty4 = (tid >> 4) << 2;
    #pragma unroll 8
    for (int k = 0; k < kcnt; k++) {
        float2 a01 = *(const float2*)&As[k][ty4];
        float2 a23 = *(const float2*)&As[k][ty4 + 2];
        ull ad0 = dup2(a01.x), ad1 = dup2(a01.y);
        ull ad2 = dup2(a23.x), ad3 = dup2(a23.y);
        ull w_[4];
        #pragma unroll
        for (int m = 0; m < 4; m++)
            w_[m] = *(const ull*)&Ws[k][m * 32 + tx * 2];
        #pragma unroll
        for (int m = 0; m < 4; m++) {
            fma2(acc[0][m], ad0, w_[m]);
            fma2(acc[1][m], ad1, w_[m]);
            fma2(acc[2][m], ad2, w_[m]);
            fma2(acc[3][m], ad3, w_[m]);
        }
    }
}

__device__ __forceinline__ void store_tile(float* __restrict__ Cp, int ldC,
                                           int n0, ull acc[4][4])
{
    const int tid = threadIdx.x;
    const int tx = tid & 15;
    const int ty4 = (tid >> 4) << 2;
    #pragma unroll
    for (int i = 0; i < 4; i++) {
        int b = ty4 + i;
        #pragma unroll
        for (int m = 0; m < 4; m++)
            *(float2*)&Cp[(size_t)b * ldC + n0 + m * 32 + tx * 2] =
                *(float2*)&acc[i][m];
    }
}

__global__ __launch_bounds__(256, 1) void rnn_persistent(
    const float* __restrict__ eps, const float* __restrict__ w_hh,
    const float* __restrict__ w_g, const float* __restrict__ b_g,
    float* __restrict__ o_seq, float* __restrict__ o_prob,
    float* __restrict__ o_mu, float* __restrict__ o_std)
{
    extern __shared__ unsigned char smraw[];
    SmemR& sm = *(SmemR*)smraw;
    const int cta = blockIdx.x;
    const int tid = threadIdx.x;
    const float LPC = -0.5f * 1.8378770664093453f * (float)Hz;

    const int n01 = (cta & 7)  * 128, kb1 = (cta >> 3) * 64;   // GEMM1 tile
    const int n02 = (cta & 15) * 128, kb2 = (cta >> 4) * 128;  // GEMM2 tile
    const size_t p1off = (size_t)(cta >> 3) * (Bz * Hz);
    const size_t p2off = (size_t)(cta >> 4) * (Bz * H2z);

    // zero recurrent state
    g_h[cta * 512 + tid]       = 0.0f;
    g_h[cta * 512 + tid + 256] = 0.0f;

    // preload resident weight slices (once)
    for (int e = tid; e < 128 * 64; e += 256) {
        int k = e & 63, n = e >> 6;
        sm.Ws1[k][n] = __ldg(&w_hh[(size_t)(n01 + n) * 1024 + kb1 + k]);
    }
    for (int e = tid; e < 128 * 128; e += 256) {
        int k = e & 127, n = e >> 7;
        sm.Ws2[k][n] = __ldg(&w_g[(size_t)(n02 + n) * 1024 + kb2 + k]);
    }
    grid_sync();

    for (int t = 0; t < Tz; t++) {
        // ---- P0: o_prob(t-1) + GEMM1 partial: g_p1 = h @ w_hh^T -----------
        if (t > 0 && cta < Bz && tid == 0)
            o_prob[cta * Tz + (t - 1)] =
                __ldcg(&g_lpp[cta][0]) + __ldcg(&g_lpp[cta][1]) + LPC;
        stage_A(sm.As, g_h, kb1, 64);
        __syncthreads();
        {
            ull acc[4][4] = {};
            gemm_resident(sm.As, sm.Ws1, 64, acc);
            store_tile(g_p1 + p1off, Hz, n01, acc);
        }
        grid_sync();

        // ---- P1: combine 16 partials + xw + tanh -> g_hrnn (float2) -------
        {
            int base = cta * 512 + tid * 2;          // b*1024 + j (even)
            int b = base >> 10, j = base & 1023;
            float2 v = __ldg((const float2*)&g_xw[((size_t)b * Tz + t) * Hz + j]);
            float2 acc2 = make_float2(0.f, 0.f);
            #pragma unroll
            for (int sl = 0; sl < NS1; sl += 2) {
                float2 p0 = __ldcg((const float2*)&g_p1[(size_t)sl * (Bz * Hz) + base]);
                float2 p1 = __ldcg((const float2*)&g_p1[(size_t)(sl + 1) * (Bz * Hz) + base]);
                v.x += p0.x;    v.y += p0.y;
                acc2.x += p1.x; acc2.y += p1.y;
            }
            v.x += acc2.x; v.y += acc2.y;
            *(float2*)&g_hrnn[base] = make_float2(tanhf(v.x), tanhf(v.y));
        }
        grid_sync();

        // ---- P2: GEMM2 partial: g_p2 = h_rnn @ w_g^T ----------------------
        stage_A(sm.As, g_hrnn, kb2, 128);
        __syncthreads();
        {
            ull acc[4][4] = {};
            gemm_resident(sm.As, sm.Ws2, 128, acc);
            store_tile(g_p2 + p2off, H2z, n02, acc);
        }
        grid_sync();

        // ---- P3: epilogue, half batch-row per CTA (float2) ----------------
        {
            const int b = cta >> 1;
            const int j = (cta & 1) * 512 + tid * 2;
            float2 ss = __ldg((const float2*)&b_g[j]);
            float2 mu = __ldg((const float2*)&b_g[Hz + j]);
            #pragma unroll
            for (int sl = 0; sl < NS2; sl++) {
                const float* p = g_p2 + (size_t)sl * (Bz * H2z) + (size_t)b * H2z;
                float2 a = __ldcg((const float2*)&p[j]);
                float2 c = __ldcg((const float2*)&p[Hz + j]);
                ss.x += a.x; ss.y += a.y;
                mu.x += c.x; mu.y += c.y;
            }
            float sdx = (ss.x > 20.f) ? ss.x : log1pf(__expf(ss.x));
            float sdy = (ss.y > 20.f) ? ss.y : log1pf(__expf(ss.y));
            float2 e = __ldg((const float2*)&eps[((size_t)b * Tz + t) * Hz + j]);
            float2 smp = make_float2(mu.x + sdx * e.x, mu.y + sdy * e.y);
            size_t o = ((size_t)b * Tz + t) * Hz + j;
            *(float2*)&o_seq[o] = smp;
            *(float2*)&o_mu[o]  = mu;
            *(float2*)&o_std[o] = make_float2(sdx, sdy);
            *(float2*)&g_h[b * Hz + j] = smp;

            float lp = -0.5f * (e.x * e.x + e.y * e.y)
                     - __logf(sdx) - __logf(sdy);
            #pragma unroll
            for (int off = 16; off > 0; off >>= 1)
                lp += __shfl_xor_sync(0xffffffffu, lp, off);
            if ((tid & 31) == 0) sm.red[tid >> 5] = lp;
            __syncthreads();
            if (tid == 0) {
                float sum = 0.0f;
                #pragma unroll
                for (int w = 0; w < 8; w++) sum += sm.red[w];
                g_lpp[b][cta & 1] = sum;
            }
        }
        grid_sync();
    }

    // final o_prob for t = 511
    if (cta < Bz && tid == 0)
        o_prob[cta * Tz + (Tz - 1)] =
            __ldcg(&g_lpp[cta][0]) + __ldcg(&g_lpp[cta][1]) + LPC;
}

// ---------------------------------------------------------------------------
extern "C" void kernel_launch(void* const* d_in, const int* in_sizes, int n_in,
                              void* d_out, int out_size)
{
    const float* x    = (const float*)d_in[0];
    const float* eps  = (const float*)d_in[1];
    const float* w_ih = (const float*)d_in[2];
    const float* w_hh = (const float*)d_in[3];
    const float* b_ih = (const float*)d_in[4];
    const float* b_hh = (const float*)d_in[5];
    const float* w_g  = (const float*)d_in[6];
    const float* b_g  = (const float*)d_in[7];

    float* out = (float*)d_out;
    float* o_seq  = out;
    float* o_prob = out + (size_t)Bz * Tz * Hz;
    float* o_mu   = o_prob + (size_t)Bz * Tz;
    float* o_std  = o_mu + (size_t)Bz * Tz * Hz;

    const int xw_smem = 384 * APAD * sizeof(__nv_bfloat16);  // 55296 B

    cudaFuncSetAttribute(rnn_persistent,
                         cudaFuncAttributeMaxDynamicSharedMemorySize,
                         (int)sizeof(SmemR));
    cudaFuncSetAttribute(xw_mma,
                         cudaFuncAttributeMaxDynamicSharedMemorySize, xw_smem);

    xw_mma<<<dim3(16, 256), 256, xw_smem>>>(x, w_ih, b_ih, b_hh);
    rnn_persistent<<<NCTA, 256, sizeof(SmemR)>>>(eps, w_hh, w_g, b_g,
                                                 o_seq, o_prob, o_mu, o_std);
}

// round 17
// speedup vs baseline: 2.2039x; 1.3368x over previous
#include <cuda_runtime.h>
#include <cuda_bf16.h>
#include <math.h>
#include <stdint.h>

#define Bz 64
#define Tz 512
#define Hz 1024
#define H2z 2048
#define NCTA 128
#define NS1 16             // GEMM1 k-slices (K=64)
#define NS2 8              // GEMM2 k-slices (K=128)
#define APAD 72            // xw kernel bf16 row stride
#define AP2 136            // persistent A / W2 bf16 row stride (128+8)
#define WP1 72             // persistent W1 bf16 row stride (64+8)

// Scratch (__device__ globals; no allocation allowed)
__device__ float g_xw[(size_t)32768 * 1024];   // [B*T, H]
__device__ float g_h[Bz * Hz];
__device__ float g_hrnn[Bz * Hz];
__device__ float g_p1[NS1 * Bz * Hz];
__device__ float g_p2[NS2 * Bz * H2z];
__device__ float g_lpp[Bz][2];
__device__ unsigned g_count, g_gen;

typedef unsigned long long ull;
__device__ __forceinline__ uint32_t smem_u32(const void* p) {
    uint32_t a;
    asm("{ .reg .u64 t; cvta.to.shared.u64 t, %1; cvt.u32.u64 %0, t; }"
        : "=r"(a) : "l"(p));
    return a;
}

// Atomic-counter grid barrier (proven R3/R7/R8).
__device__ __forceinline__ void grid_sync() {
    __syncthreads();
    if (threadIdx.x == 0) {
        unsigned g = *(volatile unsigned*)&g_gen;
        __threadfence();
        unsigned old = atomicAdd(&g_count, 1u);
        if (old == NCTA - 1) {
            g_count = 0u;
            __threadfence();
            atomicAdd(&g_gen, 1u);
        } else {
            while (*(volatile unsigned*)&g_gen == g) { }
        }
        __threadfence();
    }
    __syncthreads();
}

// ===========================================================================
// mma.sync helpers (baseline PTX)
// ===========================================================================
__device__ __forceinline__ void ldmA(uint32_t addr, uint32_t r[4]) {
    asm volatile("ldmatrix.sync.aligned.m8n8.x4.shared.b16 {%0,%1,%2,%3}, [%4];"
                 : "=r"(r[0]), "=r"(r[1]), "=r"(r[2]), "=r"(r[3]) : "r"(addr));
}
__device__ __forceinline__ void ldmB(uint32_t addr, uint32_t r[2]) {
    asm volatile("ldmatrix.sync.aligned.m8n8.x2.shared.b16 {%0,%1}, [%2];"
                 : "=r"(r[0]), "=r"(r[1]) : "r"(addr));
}
__device__ __forceinline__ void mma16816(float d[4], const uint32_t a[4],
                                         const uint32_t b[2]) {
    asm volatile(
        "mma.sync.aligned.m16n8k16.row.col.f32.bf16.bf16.f32 "
        "{%0,%1,%2,%3},{%4,%5,%6,%7},{%8,%9},{%0,%1,%2,%3};"
        : "+f"(d[0]), "+f"(d[1]), "+f"(d[2]), "+f"(d[3])
        : "r"(a[0]), "r"(a[1]), "r"(a[2]), "r"(a[3]), "r"(b[0]), "r"(b[1]));
}
__device__ __forceinline__ void split4(float4 v, uint2& hi, uint2& lo) {
    __nv_bfloat162 h0 = __floats2bfloat162_rn(v.x, v.y);
    __nv_bfloat162 h1 = __floats2bfloat162_rn(v.z, v.w);
    float2 f0 = __bfloat1622float2(h0);
    float2 f1 = __bfloat1622float2(h1);
    __nv_bfloat162 l0 = __floats2bfloat162_rn(v.x - f0.x, v.y - f0.y);
    __nv_bfloat162 l1 = __floats2bfloat162_rn(v.z - f1.x, v.w - f1.y);
    hi = make_uint2(*(uint32_t*)&h0, *(uint32_t*)&h1);
    lo = make_uint2(*(uint32_t*)&l0, *(uint32_t*)&l1);
}

// ===========================================================================
// xw_mma (R16 verbatim — passing, 2 CTAs/SM)
// ===========================================================================
__global__ __launch_bounds__(256, 2) void xw_mma(
    const float* __restrict__ x, const float* __restrict__ w_ih,
    const float* __restrict__ b_ih, const float* __restrict__ b_hh)
{
    extern __shared__ __nv_bfloat16 sb[];
    __nv_bfloat16* Ah = sb;
    __nv_bfloat16* Al = sb + 128 * APAD;
    __nv_bfloat16* Bh = sb + 256 * APAD;
    __nv_bfloat16* Bl = sb + 256 * APAD + 64 * APAD;

    const int tid = threadIdx.x;
    const int lane = tid & 31;
    const int wid = tid >> 5;
    const int m0 = blockIdx.y * 128;
    const int n0 = blockIdx.x * 64;
    const int m_w = (wid >> 1) * 32;
    const int n_w = (wid & 1) * 32;

    const uint32_t aHiB = smem_u32(Ah);
    const uint32_t aLoB = smem_u32(Al);
    const uint32_t bHiB = smem_u32(Bh);
    const uint32_t bLoB = smem_u32(Bl);

    const uint32_t aoff0 = (uint32_t)((m_w + (lane & 15)) * (APAD * 2) + (lane >> 4) * 16);
    const uint32_t aoff1 = aoff0 + 16 * (APAD * 2);
    const uint32_t boffbase = (uint32_t)((n_w + (lane & 7)) * (APAD * 2)
                                         + ((lane >> 3) & 1) * 16);

    float acc[2][4][4] = {};

    for (int c = 0; c < 16; c++) {
        const int k0 = c * 64;
        __syncthreads();
        #pragma unroll
        for (int i = 0; i < 8; i++) {
            int idx = tid + i * 256;
            int row = idx >> 4, kq = idx & 15;
            float4 v = __ldg((const float4*)&x[(size_t)(m0 + row) * 1024 + k0 + kq * 4]);
            uint2 hi, lo;
            split4(v, hi, lo);
            *(uint2*)&Ah[row * APAD + kq * 4] = hi;
            *(uint2*)&Al[row * APAD + kq * 4] = lo;
        }
        #pragma unroll
        for (int i = 0; i < 4; i++) {
            int idx = tid + i * 256;
            int row = idx >> 4, kq = idx & 15;
            float4 v = __ldg((const float4*)&w_ih[(size_t)(n0 + row) * 1024 + k0 + kq * 4]);
            uint2 hi, lo;
            split4(v, hi, lo);
            *(uint2*)&Bh[row * APAD + kq * 4] = hi;
            *(uint2*)&Bl[row * APAD + kq * 4] = lo;
        }
        __syncthreads();

        #pragma unroll
        for (int kk = 0; kk < 4; kk++) {
            const uint32_t kb = kk * 32;
            uint32_t ah0[4], ah1[4], al0[4], al1[4];
            ldmA(aHiB + aoff0 + kb, ah0);
            ldmA(aHiB + aoff1 + kb, ah1);
            ldmA(aLoB + aoff0 + kb, al0);
            ldmA(aLoB + aoff1 + kb, al1);
            uint32_t bh[4][2], bl[4][2];
            #pragma unroll
            for (int fn = 0; fn < 4; fn++) {
                ldmB(bHiB + boffbase + fn * 8 * (APAD * 2) + kb, bh[fn]);
                ldmB(bLoB + boffbase + fn * 8 * (APAD * 2) + kb, bl[fn]);
            }
            #pragma unroll
            for (int fn = 0; fn < 4; fn++) {
                mma16816(acc[0][fn], ah0, bh[fn]);
                mma16816(acc[1][fn], ah1, bh[fn]);
                mma16816(acc[0][fn], ah0, bl[fn]);
                mma16816(acc[1][fn], ah1, bl[fn]);
                mma16816(acc[0][fn], al0, bh[fn]);
                mma16816(acc[1][fn], al1, bh[fn]);
            }
        }
    }

    #pragma unroll
    for (int fm = 0; fm < 2; fm++) {
        int mr = m0 + m_w + fm * 16 + (lane >> 2);
        #pragma unroll
        for (int fn = 0; fn < 4; fn++) {
            int nc = n0 + n_w + fn * 8 + 2 * (lane & 3);
            float bx = __ldg(&b_ih[nc])     + __ldg(&b_hh[nc]);
            float by = __ldg(&b_ih[nc + 1]) + __ldg(&b_hh[nc + 1]);
            *(float2*)&g_xw[(size_t)mr * Hz + nc] =
                make_float2(acc[fm][fn][0] + bx, acc[fm][fn][1] + by);
            *(float2*)&g_xw[(size_t)(mr + 8) * Hz + nc] =
                make_float2(acc[fm][fn][2] + bx, acc[fm][fn][3] + by);
        }
    }
}

// ===========================================================================
// Persistent recurrent kernel — R8 structure, GEMMs ported to mma.sync.
// SMEM: split-bf16 resident weights + split-bf16 A staging (~142 KB).
// ===========================================================================
struct SmemR {
    __nv_bfloat16 Ah[64][AP2];     // staged A hi [row][k]
    __nv_bfloat16 Al[64][AP2];     // staged A lo
    __nv_bfloat16 W1h[128][WP1];   // w_hh slice hi [n][k] (K=64)
    __nv_bfloat16 W1l[128][WP1];
    __nv_bfloat16 W2h[128][AP2];   // w_g slice hi [n][k] (K=128)
    __nv_bfloat16 W2l[128][AP2];
    float red[8];
};

// Stage A[64][kcnt] fp32 -> split bf16 rows (row-major [row][k]).
__device__ __forceinline__ void stage_A_split(
    __nv_bfloat16 (*Ah)[AP2], __nv_bfloat16 (*Al)[AP2],
    const float* __restrict__ A, int kb, int kcnt)
{
    const int tid = threadIdx.x;
    const int row = tid >> 2;
    const int cb = (tid & 3) * (kcnt >> 2);     // float offset
    for (int c = 0; c < (kcnt >> 2); c += 4) {
        float4 v = __ldcg((const float4*)&A[row * 1024 + kb + cb + c]);
        uint2 hi, lo;
        split4(v, hi, lo);
        *(uint2*)&Ah[row][cb + c] = hi;
        *(uint2*)&Al[row][cb + c] = lo;
    }
}

// mma GEMM: C[64][128] = A[64][K] @ W[128][K]^T, 8 warps (2m x 4n).
// kchunks = K/16. Wstride = bf16 row stride of W arrays.
template<int KCH, int WSTRIDE>
__device__ __forceinline__ void gemm_mma(
    uint32_t aHi, uint32_t aLo, uint32_t wHi, uint32_t wLo,
    float acc[2][4][4])
{
    const int tid = threadIdx.x;
    const int lane = tid & 31;
    const int wid = tid >> 5;
    const int m_w = (wid >> 2) * 32;          // 0 or 32
    const int n_w = (wid & 3) * 32;           // 0,32,64,96

    const uint32_t aoff0 = (uint32_t)((m_w + (lane & 15)) * (AP2 * 2) + (lane >> 4) * 16);
    const uint32_t aoff1 = aoff0 + 16 * (AP2 * 2);
    const uint32_t boffb = (uint32_t)((n_w + (lane & 7)) * (WSTRIDE * 2)
                                      + ((lane >> 3) & 1) * 16);
    #pragma unroll
    for (int kk = 0; kk < KCH; kk++) {
        const uint32_t kb = kk * 32;
        uint32_t ah0[4], ah1[4], al0[4], al1[4];
        ldmA(aHi + aoff0 + kb, ah0);
        ldmA(aHi + aoff1 + kb, ah1);
        ldmA(aLo + aoff0 + kb, al0);
        ldmA(aLo + aoff1 + kb, al1);
        uint32_t bh[4][2], bl[4][2];
        #pragma unroll
        for (int fn = 0; fn < 4; fn++) {
            ldmB(wHi + boffb + fn * 8 * (WSTRIDE * 2) + kb, bh[fn]);
            ldmB(wLo + boffb + fn * 8 * (WSTRIDE * 2) + kb, bl[fn]);
        }
        #pragma unroll
        for (int fn = 0; fn < 4; fn++) {
            mma16816(acc[0][fn], ah0, bh[fn]);
            mma16816(acc[1][fn], ah1, bh[fn]);
            mma16816(acc[0][fn], ah0, bl[fn]);
            mma16816(acc[1][fn], ah1, bl[fn]);
            mma16816(acc[0][fn], al0, bh[fn]);
            mma16816(acc[1][fn], al1, bh[fn]);
        }
    }
}

// store mma accumulators to partial buffer
__device__ __forceinline__ void store_mma(float* __restrict__ Cp, int ldC,
                                          int n0, float acc[2][4][4])
{
    const int tid = threadIdx.x;
    const int lane = tid & 31;
    const int wid = tid >> 5;
    const int m_w = (wid >> 2) * 32;
    const int n_w = (wid & 3) * 32;
    #pragma unroll
    for (int fm = 0; fm < 2; fm++) {
        int b = m_w + fm * 16 + (lane >> 2);
        #pragma unroll
        for (int fn = 0; fn < 4; fn++) {
            int n = n0 + n_w + fn * 8 + 2 * (lane & 3);
            *(float2*)&Cp[(size_t)b * ldC + n] =
                make_float2(acc[fm][fn][0], acc[fm][fn][1]);
            *(float2*)&Cp[(size_t)(b + 8) * ldC + n] =
                make_float2(acc[fm][fn][2], acc[fm][fn][3]);
        }
    }
}

__global__ __launch_bounds__(256, 1) void rnn_persistent(
    const float* __restrict__ eps, const float* __restrict__ w_hh,
    const float* __restrict__ w_g, const float* __restrict__ b_g,
    float* __restrict__ o_seq, float* __restrict__ o_prob,
    float* __restrict__ o_mu, float* __restrict__ o_std)
{
    extern __shared__ unsigned char smraw[];
    SmemR& sm = *(SmemR*)smraw;
    const int cta = blockIdx.x;
    const int tid = threadIdx.x;
    const float LPC = -0.5f * 1.8378770664093453f * (float)Hz;

    const int n01 = (cta & 7)  * 128, kb1 = (cta >> 3) * 64;   // GEMM1 tile
    const int n02 = (cta & 15) * 128, kb2 = (cta >> 4) * 128;  // GEMM2 tile
    const size_t p1off = (size_t)(cta >> 3) * (Bz * Hz);
    const size_t p2off = (size_t)(cta >> 4) * (Bz * H2z);

    const uint32_t aHi = smem_u32(sm.Ah);
    const uint32_t aLo = smem_u32(sm.Al);
    const uint32_t w1Hi = smem_u32(sm.W1h);
    const uint32_t w1Lo = smem_u32(sm.W1l);
    const uint32_t w2Hi = smem_u32(sm.W2h);
    const uint32_t w2Lo = smem_u32(sm.W2l);

    // zero recurrent state
    g_h[cta * 512 + tid]       = 0.0f;
    g_h[cta * 512 + tid + 256] = 0.0f;

    // preload + split weight slices (once)
    for (int e = tid; e < 128 * 16; e += 256) {      // W1: 128 n x 16 float4
        int n = e >> 4, q = e & 15;
        float4 v = __ldg((const float4*)&w_hh[(size_t)(n01 + n) * 1024 + kb1 + q * 4]);
        uint2 hi, lo;
        split4(v, hi, lo);
        *(uint2*)&sm.W1h[n][q * 4] = hi;
        *(uint2*)&sm.W1l[n][q * 4] = lo;
    }
    for (int e = tid; e < 128 * 32; e += 256) {      // W2: 128 n x 32 float4
        int n = e >> 5, q = e & 31;
        float4 v = __ldg((const float4*)&w_g[(size_t)(n02 + n) * 1024 + kb2 + q * 4]);
        uint2 hi, lo;
        split4(v, hi, lo);
        *(uint2*)&sm.W2h[n][q * 4] = hi;
        *(uint2*)&sm.W2l[n][q * 4] = lo;
    }
    grid_sync();

    for (int t = 0; t < Tz; t++) {
        // ---- P0: o_prob(t-1) + GEMM1 (mma): g_p1 = h @ w_hh^T -------------
        if (t > 0 && cta < Bz && tid == 0)
            o_prob[cta * Tz + (t - 1)] =
                __ldcg(&g_lpp[cta][0]) + __ldcg(&g_lpp[cta][1]) + LPC;
        stage_A_split(sm.Ah, sm.Al, g_h, kb1, 64);
        __syncthreads();
        {
            float acc[2][4][4] = {};
            gemm_mma<4, WP1>(aHi, aLo, w1Hi, w1Lo, acc);
            store_mma(g_p1 + p1off, Hz, n01, acc);
        }
        grid_sync();

        // ---- P1: combine 16 partials + xw + tanh -> g_hrnn (float2) -------
        {
            int base = cta * 512 + tid * 2;
            int b = base >> 10, j = base & 1023;
            float2 v = __ldg((const float2*)&g_xw[((size_t)b * Tz + t) * Hz + j]);
            float2 acc2 = make_float2(0.f, 0.f);
            #pragma unroll
            for (int sl = 0; sl < NS1; sl += 2) {
                float2 p0 = __ldcg((const float2*)&g_p1[(size_t)sl * (Bz * Hz) + base]);
                float2 p1 = __ldcg((const float2*)&g_p1[(size_t)(sl + 1) * (Bz * Hz) + base]);
                v.x += p0.x;    v.y += p0.y;
                acc2.x += p1.x; acc2.y += p1.y;
            }
            v.x += acc2.x; v.y += acc2.y;
            *(float2*)&g_hrnn[base] = make_float2(tanhf(v.x), tanhf(v.y));
        }
        grid_sync();

        // ---- P2: GEMM2 (mma): g_p2 = h_rnn @ w_g^T ------------------------
        stage_A_split(sm.Ah, sm.Al, g_hrnn, kb2, 128);
        __syncthreads();
        {
            float acc[2][4][4] = {};
            gemm_mma<8, AP2>(aHi, aLo, w2Hi, w2Lo, acc);
            store_mma(g_p2 + p2off, H2z, n02, acc);
        }
        grid_sync();

        // ---- P3: epilogue, half batch-row per CTA (float2) ----------------
        {
            const int b = cta >> 1;
            const int j = (cta & 1) * 512 + tid * 2;
            float2 ss = __ldg((const float2*)&b_g[j]);
            float2 mu = __ldg((const float2*)&b_g[Hz + j]);
            #pragma unroll
            for (int sl = 0; sl < NS2; sl++) {
                const float* p = g_p2 + (size_t)sl * (Bz * H2z) + (size_t)b * H2z;
                float2 a = __ldcg((const float2*)&p[j]);
                float2 c = __ldcg((const float2*)&p[Hz + j]);
                ss.x += a.x; ss.y += a.y;
                mu.x += c.x; mu.y += c.y;
            }
            float sdx = (ss.x > 20.f) ? ss.x : log1pf(__expf(ss.x));
            float sdy = (ss.y > 20.f) ? ss.y : log1pf(__expf(ss.y));
            float2 e = __ldg((const float2*)&eps[((size_t)b * Tz + t) * Hz + j]);
            float2 smp = make_float2(mu.x + sdx * e.x, mu.y + sdy * e.y);
            size_t o = ((size_t)b * Tz + t) * Hz + j;
            *(float2*)&o_seq[o] = smp;
            *(float2*)&o_mu[o]  = mu;
            *(float2*)&o_std[o] = make_float2(sdx, sdy);
            *(float2*)&g_h[b * Hz + j] = smp;

            float lp = -0.5f * (e.x * e.x + e.y * e.y)
                     - __logf(sdx) - __logf(sdy);
            #pragma unroll
            for (int off = 16; off > 0; off >>= 1)
                lp += __shfl_xor_sync(0xffffffffu, lp, off);
            if ((tid & 31) == 0) sm.red[tid >> 5] = lp;
            __syncthreads();
            if (tid == 0) {
                float sum = 0.0f;
                #pragma unroll
                for (int w = 0; w < 8; w++) sum += sm.red[w];
                g_lpp[b][cta & 1] = sum;
            }
        }
        grid_sync();
    }

    // final o_prob for t = 511
    if (cta < Bz && tid == 0)
        o_prob[cta * Tz + (Tz - 1)] =
            __ldcg(&g_lpp[cta][0]) + __ldcg(&g_lpp[cta][1]) + LPC;
}

// ---------------------------------------------------------------------------
extern "C" void kernel_launch(void* const* d_in, const int* in_sizes, int n_in,
                              void* d_out, int out_size)
{
    const float* x    = (const float*)d_in[0];
    const float* eps  = (const float*)d_in[1];
    const float* w_ih = (const float*)d_in[2];
    const float* w_hh = (const float*)d_in[3];
    const float* b_ih = (const float*)d_in[4];
    const float* b_hh = (const float*)d_in[5];
    const float* w_g  = (const float*)d_in[6];
    const float* b_g  = (const float*)d_in[7];

    float* out = (float*)d_out;
    float* o_seq  = out;
    float* o_prob = out + (size_t)Bz * Tz * Hz;
    float* o_mu   = o_prob + (size_t)Bz * Tz;
    float* o_std  = o_mu + (size_t)Bz * Tz * Hz;

    const int xw_smem = 384 * APAD * sizeof(__nv_bfloat16);

    cudaFuncSetAttribute(rnn_persistent,
                         cudaFuncAttributeMaxDynamicSharedMemorySize,
                         (int)sizeof(SmemR));
    cudaFuncSetAttribute(xw_mma,
                         cudaFuncAttributeMaxDynamicSharedMemorySize, xw_smem);

    xw_mma<<<dim3(16, 256), 256, xw_smem>>>(x, w_ih, b_ih, b_hh);
    rnn_persistent<<<NCTA, 256, sizeof(SmemR)>>>(eps, w_hh, w_g, b_g,
                                                 o_seq, o_prob, o_mu, o_std);
}